// round 3
// baseline (speedup 1.0000x reference)
#include <cuda_runtime.h>
#include <math.h>
#include <stdint.h>

#define Bq 16
#define Tq 512
#define Eq 100
#define Hq 500
#define G4 2000
#define NT 32
#define NEGV (-10000.0f)

#define RBLK 125
#define RTHR 128

typedef unsigned long long ull;

// ---------------- device scratch (no allocations allowed) ----------------
__device__ float g_xs[Tq * Bq * Eq];                    // [t][b][e]
__device__ float g_A0[2u * Tq * Bq * G4];               // input proj layer0, per dir
__device__ float g_A1[2u * Tq * Bq * G4];               // input proj layer1, per dir
__device__ float g_out0[Tq * Bq * 2 * Hq];              // [t][b][dir*H + j]
__device__ float g_out1[Tq * Bq * 2 * Hq];
__device__ float g_y[Tq * Bq * NT];                     // emissions, row = t*B+b
__device__ float g_hbuf[2 * 2 * Bq * 512];              // [d][pp][b][512]
__device__ float g_gold[Bq];
__device__ float g_Z[Bq];
__device__ unsigned g_barcnt;
__device__ volatile unsigned g_barrel;

// ---------------- helpers ----------------
__device__ __forceinline__ float sigm_f(float v) {
    return __fdividef(1.0f, 1.0f + __expf(-v));
}
__device__ __forceinline__ float tanh_f(float v) {
    return 1.0f - __fdividef(2.0f, __expf(2.0f * v) + 1.0f);
}
// packed 2xfp32 FMA (FFMA2) — PTX-only on sm_103a
__device__ __forceinline__ ull fma2(ull a, ull b, ull c) {
    ull d;
    asm("fma.rn.f32x2 %0, %1, %2, %3;" : "=l"(d) : "l"(a), "l"(b), "l"(c));
    return d;
}
__device__ __forceinline__ ull pk2(float a, float b) {
    ull r;
    asm("mov.b64 %0, {%1, %2};" : "=l"(r) : "f"(a), "f"(b));
    return r;
}
__device__ __forceinline__ float2 up2(ull v) {
    float2 r;
    asm("mov.b64 {%0, %1}, %2;" : "=f"(r.x), "=f"(r.y) : "l"(v));
    return r;
}

__global__ void k_reset() { g_barcnt = 0u; g_barrel = 0u; }

// ---------------- embedding: xs[t][b][e] = embed_W[x[b][t]][e] ----------------
__global__ void k_embed(const int* __restrict__ x, const float* __restrict__ embw) {
    int idx = blockIdx.x * blockDim.x + threadIdx.x;
    if (idx >= Tq * Bq * Eq) return;
    int e = idx % Eq;
    int rb = idx / Eq;
    int b = rb % Bq;
    int t = rb / Bq;
    int row = x[b * Tq + t];
    g_xs[idx] = embw[(size_t)row * Eq + e];
}

// ---------------- tiled fp32 GEMM with FFMA2: C[d][M,N] = X[M,K] @ W[d][N,K]^T + b1[d]+b2[d] ----------------
__global__ __launch_bounds__(256) void k_gemm(int lay,
                                              const float* __restrict__ W,
                                              const float* __restrict__ b1,
                                              const float* __restrict__ b2) {
    const int M = Tq * Bq;
    const int N = G4;
    const int K = (lay == 0) ? Eq : (2 * Hq);
    const float* X = (lay == 0) ? g_xs : g_out0;
    float* C = (lay == 0) ? g_A0 : g_A1;

    __shared__ float sX[16][64];
    __shared__ float sW[16][64];

    int d = blockIdx.z;
    const float* Wd = W + (size_t)d * N * K;
    const float* b1d = b1 + (size_t)d * N;
    const float* b2d = b2 + (size_t)d * N;
    float* Cd = C + (size_t)d * M * N;

    int m0 = blockIdx.y * 64, n0 = blockIdx.x * 64;
    int tid = threadIdx.x;
    int lr = tid >> 2;          // 0..63
    int lc = (tid & 3) * 4;     // 0,4,8,12
    int tx = tid & 15, ty = tid >> 4;

    ull acc2[4][4];
#pragma unroll
    for (int i = 0; i < 4; i++)
#pragma unroll
        for (int j = 0; j < 4; j++) acc2[i][j] = 0ull;

    for (int kt = 0; kt < K; kt += 16) {
        float4 xv = make_float4(0.f, 0.f, 0.f, 0.f);
        if (kt + lc < K) xv = *(const float4*)&X[(size_t)(m0 + lr) * K + kt + lc];
        float4 wv = make_float4(0.f, 0.f, 0.f, 0.f);
        if ((n0 + lr) < N && (kt + lc) < K) wv = *(const float4*)&Wd[(size_t)(n0 + lr) * K + kt + lc];
        __syncthreads();
        sX[lc + 0][lr] = xv.x; sX[lc + 1][lr] = xv.y; sX[lc + 2][lr] = xv.z; sX[lc + 3][lr] = xv.w;
        sW[lc + 0][lr] = wv.x; sW[lc + 1][lr] = wv.y; sW[lc + 2][lr] = wv.z; sW[lc + 3][lr] = wv.w;
        __syncthreads();
#pragma unroll
        for (int kp = 0; kp < 8; kp++) {
            float4 xl = *(const float4*)&sX[2 * kp + 0][ty * 4];
            float4 xh = *(const float4*)&sX[2 * kp + 1][ty * 4];
            float4 wl = *(const float4*)&sW[2 * kp + 0][tx * 4];
            float4 wh = *(const float4*)&sW[2 * kp + 1][tx * 4];
            ull xp[4] = {pk2(xl.x, xh.x), pk2(xl.y, xh.y), pk2(xl.z, xh.z), pk2(xl.w, xh.w)};
            ull wp[4] = {pk2(wl.x, wh.x), pk2(wl.y, wh.y), pk2(wl.z, wh.z), pk2(wl.w, wh.w)};
#pragma unroll
            for (int i = 0; i < 4; i++)
#pragma unroll
                for (int j = 0; j < 4; j++)
                    acc2[i][j] = fma2(xp[i], wp[j], acc2[i][j]);
        }
    }

#pragma unroll
    for (int i = 0; i < 4; i++) {
        int row = m0 + ty * 4 + i;
#pragma unroll
        for (int j = 0; j < 4; j++) {
            int col = n0 + tx * 4 + j;
            if (col < N) {
                float2 p = up2(acc2[i][j]);
                Cd[(size_t)row * N + col] = p.x + p.y + b1d[col] + b2d[col];
            }
        }
    }
}

// ---------------- persistent bidirectional LSTM layer ----------------
// 125 blocks x 128 threads; block owns hidden units j0..j0+3 for BOTH directions.
// thread: d = tid>>6, jj = (tid>>4)&3, b = tid&15 — computes 4 gate dots of length 500.
__device__ __forceinline__ void gbar(unsigned want) {
    __syncthreads();
    if (threadIdx.x == 0) {
        __threadfence();
        unsigned old = atomicAdd(&g_barcnt, 1u);
        if (old == want * RBLK - 1u) {
            g_barrel = want;               // release (volatile store, post-atomic)
        } else {
            while (g_barrel < want) { }    // plain L2 volatile poll — no atomics
        }
        __threadfence();
    }
    __syncthreads();
}

__global__ __launch_bounds__(RTHR, 1) void k_lstm(int lay,
                                                  const float* __restrict__ Whh,
                                                  const float* __restrict__ h0,
                                                  const float* __restrict__ c0,
                                                  const int* __restrict__ x) {
    extern __shared__ float sm[];
    float* sW = sm;          // [d][jj][g][500]  -> 16000 floats
    float* sh = sm + 16000;  // [d][b][500]      -> 16000 floats

    const float* A = (lay == 0) ? g_A0 : g_A1;
    float* outp = (lay == 0) ? g_out0 : g_out1;
    const int hbase = lay * 2;

    int tid = threadIdx.x;
    int d = tid >> 6;
    int jj = (tid >> 4) & 3;
    int b = tid & 15;
    int j0 = blockIdx.x * 4;
    int j = j0 + jj;

    // load Whh slices: sW[((d*4+jj)*4+g)*500 + i]
    for (int idx = tid; idx < 16000; idx += RTHR) {
        int dd = idx / 8000;
        int r = idx % 8000;
        int jg = r / 500;
        int i = r % 500;
        int jjj = jg >> 2;
        int g = jg & 3;
        sW[idx] = Whh[((size_t)dd * G4 + g * Hq + (j0 + jjj)) * Hq + i];
    }

    float hreg = h0[((size_t)(hbase + d) * Bq + b) * Hq + j];
    float creg = c0[((size_t)(hbase + d) * Bq + b) * Hq + j];

    // publish initial h to ping-pong buffer 0
    g_hbuf[((d * 2 + 0) * Bq + b) * 512 + j] = hreg;
    unsigned bstep = 1;
    gbar(bstep++);

    const float* Ad = A + (size_t)d * Tq * Bq * G4;
    int base = ((d * 4 + jj) * 4) * 500;
    const ulonglong2* w0p = (const ulonglong2*)&sW[base + 0];
    const ulonglong2* w1p = (const ulonglong2*)&sW[base + 500];
    const ulonglong2* w2p = (const ulonglong2*)&sW[base + 1000];
    const ulonglong2* w3p = (const ulonglong2*)&sW[base + 1500];

    int pp = 0;
    for (int s = 0; s < Tq; s++) {
        // prefetch gate pre-activations + mask early (overlaps staging + dot)
        int t = d ? (Tq - 1 - s) : s;
        size_t arow = ((size_t)t * Bq + b) * G4 + j;
        float gi0 = __ldg(&Ad[arow + 0 * Hq]);
        float gf0 = __ldg(&Ad[arow + 1 * Hq]);
        float gg0 = __ldg(&Ad[arow + 2 * Hq]);
        float go0 = __ldg(&Ad[arow + 3 * Hq]);
        int xv = __ldg(&x[b * Tq + t]);

        // stage h[d][b][:] from global ping-pong (L2-coherent loads)
        for (int q = tid; q < 4000; q += RTHR) {
            int dd = q / 2000;
            int r = q % 2000;
            int bb = r / 125;
            int i4 = r % 125;
            float4 v = __ldcg((const float4*)&g_hbuf[((dd * 2 + pp) * Bq + bb) * 512 + i4 * 4]);
            *(float4*)&sh[(dd * Bq + bb) * 500 + i4 * 4] = v;
        }
        __syncthreads();

        const ulonglong2* hp = (const ulonglong2*)&sh[(d * Bq + b) * 500];
        ull ac0a = 0ull, ac0b = 0ull, ac1a = 0ull, ac1b = 0ull;
        ull ac2a = 0ull, ac2b = 0ull, ac3a = 0ull, ac3b = 0ull;
#pragma unroll 5
        for (int ii = 0; ii < 125; ii++) {
            ulonglong2 hv = hp[ii];
            ulonglong2 w0 = w0p[ii], w1 = w1p[ii], w2 = w2p[ii], w3 = w3p[ii];
            ac0a = fma2(hv.x, w0.x, ac0a); ac0b = fma2(hv.y, w0.y, ac0b);
            ac1a = fma2(hv.x, w1.x, ac1a); ac1b = fma2(hv.y, w1.y, ac1b);
            ac2a = fma2(hv.x, w2.x, ac2a); ac2b = fma2(hv.y, w2.y, ac2b);
            ac3a = fma2(hv.x, w3.x, ac3a); ac3b = fma2(hv.y, w3.y, ac3b);
        }

        float2 p0a = up2(ac0a), p0b = up2(ac0b);
        float2 p1a = up2(ac1a), p1b = up2(ac1b);
        float2 p2a = up2(ac2a), p2b = up2(ac2b);
        float2 p3a = up2(ac3a), p3b = up2(ac3b);
        float gi = (p0a.x + p0a.y) + (p0b.x + p0b.y) + gi0;
        float gf = (p1a.x + p1a.y) + (p1b.x + p1b.y) + gf0;
        float gg = (p2a.x + p2a.y) + (p2b.x + p2b.y) + gg0;
        float go = (p3a.x + p3a.y) + (p3b.x + p3b.y) + go0;

        float cn = sigm_f(gf) * creg + sigm_f(gi) * tanh_f(gg);
        float hn = sigm_f(go) * tanh_f(cn);

        bool m = xv > 0;
        outp[((size_t)t * Bq + b) * (2 * Hq) + d * Hq + j] = m ? hn : 0.0f;
        if (m) { creg = cn; hreg = hn; }

        g_hbuf[((d * 2 + (pp ^ 1)) * Bq + b) * 512 + j] = hreg;
        gbar(bstep++);
        pp ^= 1;
    }
}

// ---------------- output projection: y[row][tag] = out1[row] . W_out[tag] + b_out ----------------
__global__ __launch_bounds__(256) void k_outproj(const float* __restrict__ Wo,
                                                 const float* __restrict__ bo) {
    int r0 = blockIdx.x * 8;
    int tag = threadIdx.x & 31;
    int part = threadIdx.x >> 5;  // 0..7, each covers 125 of 1000
    float acc[8];
#pragma unroll
    for (int r = 0; r < 8; r++) acc[r] = 0.0f;

    const float* w = Wo + (size_t)tag * 1000 + part * 125;
    for (int i = 0; i < 125; i++) {
        float wv = __ldg(&w[i]);
        int col = part * 125 + i;
#pragma unroll
        for (int r = 0; r < 8; r++)
            acc[r] = fmaf(wv, g_out1[(size_t)(r0 + r) * 1000 + col], acc[r]);
    }

    __shared__ float red[8][8][32];
#pragma unroll
    for (int r = 0; r < 8; r++) red[part][r][tag] = acc[r];
    __syncthreads();
    if (part == 0) {
#pragma unroll
        for (int r = 0; r < 8; r++) {
            float s = bo[tag];
#pragma unroll
            for (int p = 0; p < 8; p++) s += red[p][r][tag];
            g_y[(size_t)(r0 + r) * NT + tag] = s;
        }
    }
}

// ---------------- gold path score ----------------
__global__ void k_gold(const int* __restrict__ x, const int* __restrict__ y0,
                       const float* __restrict__ trans) {
    int b = blockIdx.x;
    float s = 0.0f;
    for (int t = threadIdx.x; t < Tq; t += blockDim.x) {
        if (x[b * Tq + t] > 0) {
            int cur = y0[b * Tq + t];
            int prev = (t == 0) ? 1 : y0[b * Tq + t - 1];  // SOS = 1
            s += g_y[((size_t)t * Bq + b) * NT + cur] + trans[cur * NT + prev];
        }
    }
    __shared__ float red[256];
    red[threadIdx.x] = s;
    __syncthreads();
    for (int k = 128; k > 0; k >>= 1) {
        if (threadIdx.x < k) red[threadIdx.x] += red[threadIdx.x + k];
        __syncthreads();
    }
    if (threadIdx.x == 0) g_gold[b] = red[0];
}

// ---------------- CRF forward (log-partition) ----------------
__global__ void k_crf(const int* __restrict__ x, const float* __restrict__ trans) {
    int b = blockIdx.x;
    int tag = threadIdx.x;  // 32 threads
    __shared__ float st[NT * NT];
    __shared__ float ss[NT];
    for (int i = tag; i < NT * NT; i += 32) st[i] = trans[i];

    int len = 0;
    for (int t = tag; t < Tq; t += 32) len += (x[b * Tq + t] > 0) ? 1 : 0;
#pragma unroll
    for (int o = 16; o; o >>= 1) len += __shfl_xor_sync(0xffffffffu, len, o);

    float sc = (tag == 1) ? 0.0f : NEGV;
    ss[tag] = sc;
    __syncwarp();

    for (int t = 0; t < len; t++) {
        float emit = g_y[((size_t)t * Bq + b) * NT + tag];
        float mx = -3.4e38f;
#pragma unroll
        for (int p = 0; p < NT; p++) {
            float v = ss[p] + st[tag * NT + p];
            mx = fmaxf(mx, v);
        }
        float sum = 0.0f;
#pragma unroll
        for (int p = 0; p < NT; p++)
            sum += __expf(ss[p] + st[tag * NT + p] - mx);
        sc = emit + mx + __logf(sum);
        __syncwarp();
        ss[tag] = sc;
        __syncwarp();
    }

    float mx = sc;
#pragma unroll
    for (int o = 16; o; o >>= 1) mx = fmaxf(mx, __shfl_xor_sync(0xffffffffu, mx, o));
    float z;
    if (len < Tq) {
        z = mx + __logf(32.0f);  // score collapses to broadcast max; lse = max + ln(32)
    } else {
        float sum = __expf(sc - mx);
#pragma unroll
        for (int o = 16; o; o >>= 1) sum += __shfl_xor_sync(0xffffffffu, sum, o);
        z = mx + __logf(sum);
    }
    if (tag == 0) g_Z[b] = z;
}

__global__ void k_final(float* __restrict__ out) {
    float s = 0.0f;
    for (int b = 0; b < Bq; b++) s += g_Z[b] - g_gold[b];
    out[0] = s / (float)Bq;
}

// ---------------- host launcher ----------------
extern "C" void kernel_launch(void* const* d_in, const int* in_sizes, int n_in,
                              void* d_out, int out_size) {
    (void)in_sizes; (void)n_in; (void)out_size;
    const int*   x     = (const int*)d_in[0];
    const int*   y0    = (const int*)d_in[1];
    const float* embw  = (const float*)d_in[2];
    const float* Wih0  = (const float*)d_in[3];
    const float* Whh0  = (const float*)d_in[4];
    const float* bih0  = (const float*)d_in[5];
    const float* bhh0  = (const float*)d_in[6];
    const float* Wih1  = (const float*)d_in[7];
    const float* Whh1  = (const float*)d_in[8];
    const float* bih1  = (const float*)d_in[9];
    const float* bhh1  = (const float*)d_in[10];
    const float* W_out = (const float*)d_in[11];
    const float* b_out = (const float*)d_in[12];
    const float* trans = (const float*)d_in[13];
    const float* h0    = (const float*)d_in[14];
    const float* c0    = (const float*)d_in[15];
    float* out = (float*)d_out;

    cudaFuncSetAttribute(k_lstm, cudaFuncAttributeMaxDynamicSharedMemorySize, 131072);

    // 1. embedding
    k_embed<<<(Tq * Bq * Eq + 255) / 256, 256>>>(x, embw);

    // 2. layer-0 input projections (both dirs)
    {
        dim3 grid((G4 + 63) / 64, (Tq * Bq) / 64, 2);
        k_gemm<<<grid, 256>>>(0, Wih0, bih0, bhh0);
    }

    // 3. layer-0 bidirectional recurrence
    k_reset<<<1, 1>>>();
    k_lstm<<<RBLK, RTHR, 2 * 16000 * sizeof(float)>>>(0, Whh0, h0, c0, x);

    // 4. layer-1 input projections
    {
        dim3 grid((G4 + 63) / 64, (Tq * Bq) / 64, 2);
        k_gemm<<<grid, 256>>>(1, Wih1, bih1, bhh1);
    }

    // 5. layer-1 bidirectional recurrence
    k_reset<<<1, 1>>>();
    k_lstm<<<RBLK, RTHR, 2 * 16000 * sizeof(float)>>>(1, Whh1, h0, c0, x);

    // 6. emissions
    k_outproj<<<(Tq * Bq) / 8, 256>>>(W_out, b_out);

    // 7. gold score + CRF partition + final loss
    k_gold<<<Bq, 256>>>(x, y0, trans);
    k_crf<<<Bq, 32>>>(x, trans);
    k_final<<<1, 1>>>(out);
}

// round 4
// speedup vs baseline: 1.1893x; 1.1893x over previous
#include <cuda_runtime.h>
#include <math.h>
#include <stdint.h>

#define Bq 16
#define Tq 512
#define Eq 100
#define Hq 500
#define G4 2000
#define NT 32
#define NEGV (-10000.0f)

#define NBLK 128
#define RTHR 128

typedef unsigned long long ull;

// ---------------- device scratch ----------------
__device__ float g_xs[Tq * Bq * Eq];
__device__ float g_A0[2u * Tq * Bq * G4];
__device__ float g_A1[2u * Tq * Bq * G4];
__device__ float g_out0[Tq * Bq * 2 * Hq];
__device__ float g_out1[Tq * Bq * 2 * Hq];
__device__ float g_y[Tq * Bq * NT];
__device__ float g_hbuf[2 * 2 * Bq * 512];   // [d][pp][b][512]
__device__ float g_gold[Bq];
__device__ float g_Z[Bq];
__device__ unsigned g_barcnt;

// ---------------- helpers ----------------
__device__ __forceinline__ float sigm_f(float v) {
    return __fdividef(1.0f, 1.0f + __expf(-v));
}
__device__ __forceinline__ float tanh_f(float v) {
    return 1.0f - __fdividef(2.0f, __expf(2.0f * v) + 1.0f);
}
__device__ __forceinline__ ull fma2(ull a, ull b, ull c) {
    ull d;
    asm("fma.rn.f32x2 %0, %1, %2, %3;" : "=l"(d) : "l"(a), "l"(b), "l"(c));
    return d;
}
__device__ __forceinline__ ull pk2(float a, float b) {
    ull r;
    asm("mov.b64 %0, {%1, %2};" : "=l"(r) : "f"(a), "f"(b));
    return r;
}
__device__ __forceinline__ float2 up2(ull v) {
    float2 r;
    asm("mov.b64 {%0, %1}, %2;" : "=f"(r.x), "=f"(r.y) : "l"(v));
    return r;
}

__global__ void k_reset() { g_barcnt = 0u; }

// ---------------- embedding ----------------
__global__ void k_embed(const int* __restrict__ x, const float* __restrict__ embw) {
    int idx = blockIdx.x * blockDim.x + threadIdx.x;
    if (idx >= Tq * Bq * Eq) return;
    int e = idx % Eq;
    int rb = idx / Eq;
    int b = rb % Bq;
    int t = rb / Bq;
    int row = x[b * Tq + t];
    g_xs[idx] = embw[(size_t)row * Eq + e];
}

// ---------------- tiled fp32 GEMM, FFMA2 with pre-packed smem ----------------
// C[d][M,N] = X[M,K] @ W[d][N,K]^T + b1[d] + b2[d]
__global__ __launch_bounds__(256) void k_gemm(int lay,
                                              const float* __restrict__ W,
                                              const float* __restrict__ b1,
                                              const float* __restrict__ b2) {
    const int M = Tq * Bq;
    const int N = G4;
    const int K = (lay == 0) ? Eq : (2 * Hq);
    const float* X = (lay == 0) ? g_xs : g_out0;
    float* C = (lay == 0) ? g_A0 : g_A1;

    __shared__ ull sXp[8][64];   // [k-pair][m], packed f32x2 along K
    __shared__ ull sWp[8][64];   // [k-pair][n]

    int d = blockIdx.z;
    const float* Wd = W + (size_t)d * N * K;
    const float* b1d = b1 + (size_t)d * N;
    const float* b2d = b2 + (size_t)d * N;
    float* Cd = C + (size_t)d * M * N;

    int m0 = blockIdx.y * 64, n0 = blockIdx.x * 64;
    int tid = threadIdx.x;
    int lr = tid >> 2;          // 0..63
    int lc = (tid & 3) * 4;     // k offset 0,4,8,12
    int tx = tid & 15, ty = tid >> 4;

    ull acc2[4][4];
#pragma unroll
    for (int i = 0; i < 4; i++)
#pragma unroll
        for (int j = 0; j < 4; j++) acc2[i][j] = 0ull;

    for (int kt = 0; kt < K; kt += 16) {
        float4 xv = make_float4(0.f, 0.f, 0.f, 0.f);
        if (kt + lc < K) xv = *(const float4*)&X[(size_t)(m0 + lr) * K + kt + lc];
        float4 wv = make_float4(0.f, 0.f, 0.f, 0.f);
        if ((n0 + lr) < N && (kt + lc) < K) wv = *(const float4*)&Wd[(size_t)(n0 + lr) * K + kt + lc];
        __syncthreads();
        sXp[(lc >> 1) + 0][lr] = pk2(xv.x, xv.y);
        sXp[(lc >> 1) + 1][lr] = pk2(xv.z, xv.w);
        sWp[(lc >> 1) + 0][lr] = pk2(wv.x, wv.y);
        sWp[(lc >> 1) + 1][lr] = pk2(wv.z, wv.w);
        __syncthreads();
#pragma unroll
        for (int kp = 0; kp < 8; kp++) {
            ulonglong2 xa = *(const ulonglong2*)&sXp[kp][ty * 4 + 0];
            ulonglong2 xb = *(const ulonglong2*)&sXp[kp][ty * 4 + 2];
            ulonglong2 wa = *(const ulonglong2*)&sWp[kp][tx * 4 + 0];
            ulonglong2 wb = *(const ulonglong2*)&sWp[kp][tx * 4 + 2];
            ull xp[4] = {xa.x, xa.y, xb.x, xb.y};
            ull wp[4] = {wa.x, wa.y, wb.x, wb.y};
#pragma unroll
            for (int i = 0; i < 4; i++)
#pragma unroll
                for (int j = 0; j < 4; j++)
                    acc2[i][j] = fma2(xp[i], wp[j], acc2[i][j]);
        }
    }

#pragma unroll
    for (int i = 0; i < 4; i++) {
        int row = m0 + ty * 4 + i;
#pragma unroll
        for (int j = 0; j < 4; j++) {
            int col = n0 + tx * 4 + j;
            if (col < N) {
                float2 p = up2(acc2[i][j]);
                Cd[(size_t)row * N + col] = p.x + p.y + b1d[col] + b2d[col];
            }
        }
    }
}

// ---------------- persistent bidirectional LSTM ----------------
// 128 blocks = (2 dirs) x (2 b-groups of 8) x (32 j-groups of 16).
// thread: bl = tid&7 (batch lane), jl = tid>>3 (hidden lane); 4 gate dots of 500.
__device__ __forceinline__ void gbar(unsigned want) {
    __syncthreads();
    if (threadIdx.x == 0) {
        __threadfence();
        atomicAdd(&g_barcnt, 1u);
        while (*(volatile unsigned*)&g_barcnt < want) { __nanosleep(40); }
        __threadfence();
    }
    __syncthreads();
}

__global__ __launch_bounds__(RTHR, 1) void k_lstm(int lay,
                                                  const float* __restrict__ Whh,
                                                  const float* __restrict__ h0,
                                                  const float* __restrict__ c0,
                                                  const int* __restrict__ x) {
    extern __shared__ float sm[];
    float* sW = sm;            // [g][jl][i] : 4*16*500 = 32000 floats (128 KB)
    float* sh = sm + 32000;    // [bl][i]    : 8*500    = 4000 floats  (16 KB)

    const float* A = (lay == 0) ? g_A0 : g_A1;
    float* outp = (lay == 0) ? g_out0 : g_out1;
    const int hbase = lay * 2;

    int tid = threadIdx.x;
    int bl = tid & 7;
    int jl = tid >> 3;          // 0..15
    int bx = blockIdx.x;
    int d = bx >> 6;
    int rem = bx & 63;
    int bg = rem >> 5;          // 0..1
    int jg = rem & 31;          // 0..31
    int b0 = bg * 8;
    int j0 = jg * 16;
    int j = j0 + jl;            // may be >= 500 (padding lanes)
    int b = b0 + bl;
    bool jok = (j < Hq);

    // load Whh slice: sW[(g*16+jl2)*500 + i]
    for (int idx = tid; idx < 32000; idx += RTHR) {
        int g = idx / 8000;
        int r = idx % 8000;
        int jl2 = r / 500;
        int i = r % 500;
        int jc = j0 + jl2;
        sW[idx] = (jc < Hq) ? Whh[((size_t)d * G4 + g * Hq + jc) * Hq + i] : 0.0f;
    }

    float hreg = jok ? h0[((size_t)(hbase + d) * Bq + b) * Hq + j] : 0.0f;
    float creg = jok ? c0[((size_t)(hbase + d) * Bq + b) * Hq + j] : 0.0f;

    g_hbuf[((d * 2 + 0) * Bq + b) * 512 + j] = hreg;
    unsigned bs = 1;
    gbar(NBLK * bs); bs++;

    const float* Ad = A + (size_t)d * Tq * Bq * G4;
    const ulonglong2* w0p = (const ulonglong2*)&sW[(0 * 16 + jl) * 500];
    const ulonglong2* w1p = (const ulonglong2*)&sW[(1 * 16 + jl) * 500];
    const ulonglong2* w2p = (const ulonglong2*)&sW[(2 * 16 + jl) * 500];
    const ulonglong2* w3p = (const ulonglong2*)&sW[(3 * 16 + jl) * 500];

    int pp = 0;
    for (int s = 0; s < Tq; s++) {
        int t = d ? (Tq - 1 - s) : s;
        // prefetch gate pre-activations + mask (overlaps staging)
        size_t arow = ((size_t)t * Bq + b) * G4 + (jok ? j : 0);
        float gi0 = __ldg(&Ad[arow + 0 * Hq]);
        float gf0 = __ldg(&Ad[arow + 1 * Hq]);
        float gg0 = __ldg(&Ad[arow + 2 * Hq]);
        float go0 = __ldg(&Ad[arow + 3 * Hq]);
        int xv = __ldg(&x[b * Tq + t]);

        // stage h for this block's 8 batch rows: 1000 float4
        for (int q = tid; q < 1000; q += RTHR) {
            int bb = q / 125;
            int i4 = q % 125;
            float4 v = __ldcg((const float4*)&g_hbuf[((d * 2 + pp) * Bq + b0 + bb) * 512 + i4 * 4]);
            *(float4*)&sh[bb * 500 + i4 * 4] = v;
        }
        __syncthreads();

        const ulonglong2* hp = (const ulonglong2*)&sh[bl * 500];
        ull ac0a = 0ull, ac0b = 0ull, ac1a = 0ull, ac1b = 0ull;
        ull ac2a = 0ull, ac2b = 0ull, ac3a = 0ull, ac3b = 0ull;
#pragma unroll 5
        for (int ii = 0; ii < 125; ii++) {
            ulonglong2 hv = hp[ii];
            ulonglong2 w0 = w0p[ii], w1 = w1p[ii], w2 = w2p[ii], w3 = w3p[ii];
            ac0a = fma2(hv.x, w0.x, ac0a); ac0b = fma2(hv.y, w0.y, ac0b);
            ac1a = fma2(hv.x, w1.x, ac1a); ac1b = fma2(hv.y, w1.y, ac1b);
            ac2a = fma2(hv.x, w2.x, ac2a); ac2b = fma2(hv.y, w2.y, ac2b);
            ac3a = fma2(hv.x, w3.x, ac3a); ac3b = fma2(hv.y, w3.y, ac3b);
        }

        float2 p0a = up2(ac0a), p0b = up2(ac0b);
        float2 p1a = up2(ac1a), p1b = up2(ac1b);
        float2 p2a = up2(ac2a), p2b = up2(ac2b);
        float2 p3a = up2(ac3a), p3b = up2(ac3b);
        float gi = (p0a.x + p0a.y) + (p0b.x + p0b.y) + gi0;
        float gf = (p1a.x + p1a.y) + (p1b.x + p1b.y) + gf0;
        float gg = (p2a.x + p2a.y) + (p2b.x + p2b.y) + gg0;
        float go = (p3a.x + p3a.y) + (p3b.x + p3b.y) + go0;

        float cn = sigm_f(gf) * creg + sigm_f(gi) * tanh_f(gg);
        float hn = sigm_f(go) * tanh_f(cn);

        bool m = xv > 0;
        if (jok)
            outp[((size_t)t * Bq + b) * (2 * Hq) + d * Hq + j] = m ? hn : 0.0f;
        if (m) { creg = cn; hreg = hn; }

        g_hbuf[((d * 2 + (pp ^ 1)) * Bq + b) * 512 + j] = hreg;
        gbar(NBLK * bs); bs++;
        pp ^= 1;
    }
}

// ---------------- output projection ----------------
__global__ __launch_bounds__(256) void k_outproj(const float* __restrict__ Wo,
                                                 const float* __restrict__ bo) {
    int r0 = blockIdx.x * 8;
    int tag = threadIdx.x & 31;
    int part = threadIdx.x >> 5;
    float acc[8];
#pragma unroll
    for (int r = 0; r < 8; r++) acc[r] = 0.0f;

    const float* w = Wo + (size_t)tag * 1000 + part * 125;
    for (int i = 0; i < 125; i++) {
        float wv = __ldg(&w[i]);
        int col = part * 125 + i;
#pragma unroll
        for (int r = 0; r < 8; r++)
            acc[r] = fmaf(wv, g_out1[(size_t)(r0 + r) * 1000 + col], acc[r]);
    }

    __shared__ float red[8][8][32];
#pragma unroll
    for (int r = 0; r < 8; r++) red[part][r][tag] = acc[r];
    __syncthreads();
    if (part == 0) {
#pragma unroll
        for (int r = 0; r < 8; r++) {
            float s = bo[tag];
#pragma unroll
            for (int p = 0; p < 8; p++) s += red[p][r][tag];
            g_y[(size_t)(r0 + r) * NT + tag] = s;
        }
    }
}

// ---------------- gold path score ----------------
__global__ void k_gold(const int* __restrict__ x, const int* __restrict__ y0,
                       const float* __restrict__ trans) {
    int b = blockIdx.x;
    float s = 0.0f;
    for (int t = threadIdx.x; t < Tq; t += blockDim.x) {
        if (x[b * Tq + t] > 0) {
            int cur = y0[b * Tq + t];
            int prev = (t == 0) ? 1 : y0[b * Tq + t - 1];
            s += g_y[((size_t)t * Bq + b) * NT + cur] + trans[cur * NT + prev];
        }
    }
    __shared__ float red[256];
    red[threadIdx.x] = s;
    __syncthreads();
    for (int k = 128; k > 0; k >>= 1) {
        if (threadIdx.x < k) red[threadIdx.x] += red[threadIdx.x + k];
        __syncthreads();
    }
    if (threadIdx.x == 0) g_gold[b] = red[0];
}

// ---------------- CRF forward ----------------
__global__ void k_crf(const int* __restrict__ x, const float* __restrict__ trans) {
    int b = blockIdx.x;
    int tag = threadIdx.x;
    __shared__ float st[NT * NT];
    __shared__ float ss[NT];
    for (int i = tag; i < NT * NT; i += 32) st[i] = trans[i];

    int len = 0;
    for (int t = tag; t < Tq; t += 32) len += (x[b * Tq + t] > 0) ? 1 : 0;
#pragma unroll
    for (int o = 16; o; o >>= 1) len += __shfl_xor_sync(0xffffffffu, len, o);

    float sc = (tag == 1) ? 0.0f : NEGV;
    ss[tag] = sc;
    __syncwarp();

    for (int t = 0; t < len; t++) {
        float emit = g_y[((size_t)t * Bq + b) * NT + tag];
        float mx = -3.4e38f;
#pragma unroll
        for (int p = 0; p < NT; p++) {
            float v = ss[p] + st[tag * NT + p];
            mx = fmaxf(mx, v);
        }
        float sum = 0.0f;
#pragma unroll
        for (int p = 0; p < NT; p++)
            sum += __expf(ss[p] + st[tag * NT + p] - mx);
        sc = emit + mx + __logf(sum);
        __syncwarp();
        ss[tag] = sc;
        __syncwarp();
    }

    float mx = sc;
#pragma unroll
    for (int o = 16; o; o >>= 1) mx = fmaxf(mx, __shfl_xor_sync(0xffffffffu, mx, o));
    float z;
    if (len < Tq) {
        z = mx + __logf(32.0f);
    } else {
        float sum = __expf(sc - mx);
#pragma unroll
        for (int o = 16; o; o >>= 1) sum += __shfl_xor_sync(0xffffffffu, sum, o);
        z = mx + __logf(sum);
    }
    if (tag == 0) g_Z[b] = z;
}

__global__ void k_final(float* __restrict__ out) {
    float s = 0.0f;
    for (int b = 0; b < Bq; b++) s += g_Z[b] - g_gold[b];
    out[0] = s / (float)Bq;
}

// ---------------- host launcher ----------------
extern "C" void kernel_launch(void* const* d_in, const int* in_sizes, int n_in,
                              void* d_out, int out_size) {
    (void)in_sizes; (void)n_in; (void)out_size;
    const int*   x     = (const int*)d_in[0];
    const int*   y0    = (const int*)d_in[1];
    const float* embw  = (const float*)d_in[2];
    const float* Wih0  = (const float*)d_in[3];
    const float* Whh0  = (const float*)d_in[4];
    const float* bih0  = (const float*)d_in[5];
    const float* bhh0  = (const float*)d_in[6];
    const float* Wih1  = (const float*)d_in[7];
    const float* Whh1  = (const float*)d_in[8];
    const float* bih1  = (const float*)d_in[9];
    const float* bhh1  = (const float*)d_in[10];
    const float* W_out = (const float*)d_in[11];
    const float* b_out = (const float*)d_in[12];
    const float* trans = (const float*)d_in[13];
    const float* h0    = (const float*)d_in[14];
    const float* c0    = (const float*)d_in[15];
    float* out = (float*)d_out;

    const int lstm_smem = (32000 + 4000) * sizeof(float);  // 144 KB
    cudaFuncSetAttribute(k_lstm, cudaFuncAttributeMaxDynamicSharedMemorySize, lstm_smem);

    k_embed<<<(Tq * Bq * Eq + 255) / 256, 256>>>(x, embw);

    {
        dim3 grid((G4 + 63) / 64, (Tq * Bq) / 64, 2);
        k_gemm<<<grid, 256>>>(0, Wih0, bih0, bhh0);
    }

    k_reset<<<1, 1>>>();
    k_lstm<<<NBLK, RTHR, lstm_smem>>>(0, Whh0, h0, c0, x);

    {
        dim3 grid((G4 + 63) / 64, (Tq * Bq) / 64, 2);
        k_gemm<<<grid, 256>>>(1, Wih1, bih1, bhh1);
    }

    k_reset<<<1, 1>>>();
    k_lstm<<<NBLK, RTHR, lstm_smem>>>(1, Whh1, h0, c0, x);

    k_outproj<<<(Tq * Bq) / 8, 256>>>(W_out, b_out);

    k_gold<<<Bq, 256>>>(x, y0, trans);
    k_crf<<<Bq, 32>>>(x, trans);
    k_final<<<1, 1>>>(out);
}

// round 5
// speedup vs baseline: 1.2539x; 1.0543x over previous
#include <cuda_runtime.h>
#include <math.h>
#include <stdint.h>

#define Bq 16
#define Tq 512
#define Eq 100
#define Hq 500
#define G4 2000
#define NT 32
#define NEGV (-10000.0f)

#define NBLK 128
#define RTHR 128
#define GRPSZ 32

typedef unsigned long long ull;

// ---------------- device scratch ----------------
__device__ float g_xs[Tq * Bq * Eq];
__device__ float g_A0[2u * Tq * Bq * G4];
__device__ float g_A1[2u * Tq * Bq * G4];
__device__ float g_out0[Tq * Bq * 2 * Hq];
__device__ float g_out1[Tq * Bq * 2 * Hq];
__device__ float g_y[Tq * Bq * NT];
__device__ float g_hbuf[2 * 2 * Bq * 512];   // [d][pp][b][512]
__device__ float g_gold[Bq];
__device__ float g_Z[Bq];
__device__ unsigned g_cnt[4 * 32];           // per-group counters, 128B apart

// ---------------- helpers ----------------
__device__ __forceinline__ float sigm_f(float v) {
    return __fdividef(1.0f, 1.0f + __expf(-v));
}
__device__ __forceinline__ float tanh_f(float v) {
    return 1.0f - __fdividef(2.0f, __expf(2.0f * v) + 1.0f);
}
__device__ __forceinline__ ull fma2(ull a, ull b, ull c) {
    ull d;
    asm("fma.rn.f32x2 %0, %1, %2, %3;" : "=l"(d) : "l"(a), "l"(b), "l"(c));
    return d;
}
__device__ __forceinline__ ull pk2(float a, float b) {
    ull r;
    asm("mov.b64 %0, {%1, %2};" : "=l"(r) : "f"(a), "f"(b));
    return r;
}
__device__ __forceinline__ float2 up2(ull v) {
    float2 r;
    asm("mov.b64 {%0, %1}, %2;" : "=f"(r.x), "=f"(r.y) : "l"(v));
    return r;
}
__device__ __forceinline__ void red_release_add1(unsigned* p) {
    asm volatile("red.release.gpu.global.add.u32 [%0], 1;" :: "l"(p) : "memory");
}
__device__ __forceinline__ unsigned ld_acquire(const unsigned* p) {
    unsigned v;
    asm volatile("ld.acquire.gpu.global.u32 %0, [%1];" : "=r"(v) : "l"(p) : "memory");
    return v;
}

__global__ void k_reset() {
    if (threadIdx.x < 4 * 32) g_cnt[threadIdx.x] = 0u;
}

// ---------------- embedding ----------------
__global__ void k_embed(const int* __restrict__ x, const float* __restrict__ embw) {
    int idx = blockIdx.x * blockDim.x + threadIdx.x;
    if (idx >= Tq * Bq * Eq) return;
    int e = idx % Eq;
    int rb = idx / Eq;
    int b = rb % Bq;
    int t = rb / Bq;
    int row = x[b * Tq + t];
    g_xs[idx] = embw[(size_t)row * Eq + e];
}

// ---------------- tiled fp32 GEMM, FFMA2 with pre-packed smem ----------------
__global__ __launch_bounds__(256) void k_gemm(int lay,
                                              const float* __restrict__ W,
                                              const float* __restrict__ b1,
                                              const float* __restrict__ b2) {
    const int M = Tq * Bq;
    const int N = G4;
    const int K = (lay == 0) ? Eq : (2 * Hq);
    const float* X = (lay == 0) ? g_xs : g_out0;
    float* C = (lay == 0) ? g_A0 : g_A1;

    __shared__ ull sXp[8][64];
    __shared__ ull sWp[8][64];

    int d = blockIdx.z;
    const float* Wd = W + (size_t)d * N * K;
    const float* b1d = b1 + (size_t)d * N;
    const float* b2d = b2 + (size_t)d * N;
    float* Cd = C + (size_t)d * M * N;

    int m0 = blockIdx.y * 64, n0 = blockIdx.x * 64;
    int tid = threadIdx.x;
    int lr = tid >> 2;
    int lc = (tid & 3) * 4;
    int tx = tid & 15, ty = tid >> 4;

    ull acc2[4][4];
#pragma unroll
    for (int i = 0; i < 4; i++)
#pragma unroll
        for (int j = 0; j < 4; j++) acc2[i][j] = 0ull;

    for (int kt = 0; kt < K; kt += 16) {
        float4 xv = make_float4(0.f, 0.f, 0.f, 0.f);
        if (kt + lc < K) xv = *(const float4*)&X[(size_t)(m0 + lr) * K + kt + lc];
        float4 wv = make_float4(0.f, 0.f, 0.f, 0.f);
        if ((n0 + lr) < N && (kt + lc) < K) wv = *(const float4*)&Wd[(size_t)(n0 + lr) * K + kt + lc];
        __syncthreads();
        sXp[(lc >> 1) + 0][lr] = pk2(xv.x, xv.y);
        sXp[(lc >> 1) + 1][lr] = pk2(xv.z, xv.w);
        sWp[(lc >> 1) + 0][lr] = pk2(wv.x, wv.y);
        sWp[(lc >> 1) + 1][lr] = pk2(wv.z, wv.w);
        __syncthreads();
#pragma unroll
        for (int kp = 0; kp < 8; kp++) {
            ulonglong2 xa = *(const ulonglong2*)&sXp[kp][ty * 4 + 0];
            ulonglong2 xb = *(const ulonglong2*)&sXp[kp][ty * 4 + 2];
            ulonglong2 wa = *(const ulonglong2*)&sWp[kp][tx * 4 + 0];
            ulonglong2 wb = *(const ulonglong2*)&sWp[kp][tx * 4 + 2];
            ull xp[4] = {xa.x, xa.y, xb.x, xb.y};
            ull wp[4] = {wa.x, wa.y, wb.x, wb.y};
#pragma unroll
            for (int i = 0; i < 4; i++)
#pragma unroll
                for (int j = 0; j < 4; j++)
                    acc2[i][j] = fma2(xp[i], wp[j], acc2[i][j]);
        }
    }

#pragma unroll
    for (int i = 0; i < 4; i++) {
        int row = m0 + ty * 4 + i;
#pragma unroll
        for (int j = 0; j < 4; j++) {
            int col = n0 + tx * 4 + j;
            if (col < N) {
                float2 p = up2(acc2[i][j]);
                Cd[(size_t)row * N + col] = p.x + p.y + b1d[col] + b2d[col];
            }
        }
    }
}

// ---------------- persistent bidirectional LSTM ----------------
// 128 blocks = (2 dirs) x (2 b-groups of 8) x (32 j-groups of 16).
// Sync: 4 independent group barriers (release-add / acquire-poll, monotonic).
__device__ __forceinline__ void gbar(unsigned* cnt, unsigned want) {
    __syncthreads();
    if (threadIdx.x == 0) {
        red_release_add1(cnt);
        int spins = 0;
        while (ld_acquire(cnt) < want) {
            if (++spins > 16) __nanosleep(20);
        }
    }
    __syncthreads();
}

__global__ __launch_bounds__(RTHR, 1) void k_lstm(int lay,
                                                  const float* __restrict__ Whh,
                                                  const float* __restrict__ h0,
                                                  const float* __restrict__ c0,
                                                  const int* __restrict__ x) {
    extern __shared__ float sm[];
    float* sW = sm;            // [g][jl][i] : 4*16*500 = 32000 floats (128 KB)
    float* sh = sm + 32000;    // [bl][i]    : 8*500    = 4000 floats  (16 KB)

    const float* A = (lay == 0) ? g_A0 : g_A1;
    float* outp = (lay == 0) ? g_out0 : g_out1;
    const int hbase = lay * 2;

    int tid = threadIdx.x;
    int bl = tid & 7;
    int jl = tid >> 3;          // 0..15
    int bx = blockIdx.x;
    int d = bx >> 6;
    int rem = bx & 63;
    int bg = rem >> 5;          // 0..1
    int jg = rem & 31;          // 0..31
    int b0 = bg * 8;
    int j0 = jg * 16;
    int j = j0 + jl;
    int b = b0 + bl;
    bool jok = (j < Hq);
    unsigned* cnt = &g_cnt[(d * 2 + bg) * 32];

    // load Whh slice: sW[(g*16+jl2)*500 + i]
    for (int idx = tid; idx < 32000; idx += RTHR) {
        int g = idx / 8000;
        int r = idx % 8000;
        int jl2 = r / 500;
        int i = r % 500;
        int jc = j0 + jl2;
        sW[idx] = (jc < Hq) ? Whh[((size_t)d * G4 + g * Hq + jc) * Hq + i] : 0.0f;
    }

    float hreg = jok ? h0[((size_t)(hbase + d) * Bq + b) * Hq + j] : 0.0f;
    float creg = jok ? c0[((size_t)(hbase + d) * Bq + b) * Hq + j] : 0.0f;

    g_hbuf[((d * 2 + 0) * Bq + b) * 512 + j] = hreg;
    unsigned bs = 1;
    gbar(cnt, GRPSZ * bs); bs++;

    const float* Ad = A + (size_t)d * Tq * Bq * G4;
    const ulonglong2* w0p = (const ulonglong2*)&sW[(0 * 16 + jl) * 500];
    const ulonglong2* w1p = (const ulonglong2*)&sW[(1 * 16 + jl) * 500];
    const ulonglong2* w2p = (const ulonglong2*)&sW[(2 * 16 + jl) * 500];
    const ulonglong2* w3p = (const ulonglong2*)&sW[(3 * 16 + jl) * 500];

    int pp = 0;
    for (int s = 0; s < Tq; s++) {
        int t = d ? (Tq - 1 - s) : s;
        size_t arow = ((size_t)t * Bq + b) * G4 + (jok ? j : 0);
        float gi0 = __ldg(&Ad[arow + 0 * Hq]);
        float gf0 = __ldg(&Ad[arow + 1 * Hq]);
        float gg0 = __ldg(&Ad[arow + 2 * Hq]);
        float go0 = __ldg(&Ad[arow + 3 * Hq]);
        int xv = __ldg(&x[b * Tq + t]);

        // stage h for this block's 8 batch rows: 1000 float4
        for (int q = tid; q < 1000; q += RTHR) {
            int bb = q / 125;
            int i4 = q % 125;
            float4 v = __ldcg((const float4*)&g_hbuf[((d * 2 + pp) * Bq + b0 + bb) * 512 + i4 * 4]);
            *(float4*)&sh[bb * 500 + i4 * 4] = v;
        }
        __syncthreads();

        const ulonglong2* hp = (const ulonglong2*)&sh[bl * 500];
        ull ac0a = 0ull, ac0b = 0ull, ac1a = 0ull, ac1b = 0ull;
        ull ac2a = 0ull, ac2b = 0ull, ac3a = 0ull, ac3b = 0ull;
#pragma unroll 5
        for (int ii = 0; ii < 125; ii++) {
            ulonglong2 hv = hp[ii];
            ulonglong2 w0 = w0p[ii], w1 = w1p[ii], w2 = w2p[ii], w3 = w3p[ii];
            ac0a = fma2(hv.x, w0.x, ac0a); ac0b = fma2(hv.y, w0.y, ac0b);
            ac1a = fma2(hv.x, w1.x, ac1a); ac1b = fma2(hv.y, w1.y, ac1b);
            ac2a = fma2(hv.x, w2.x, ac2a); ac2b = fma2(hv.y, w2.y, ac2b);
            ac3a = fma2(hv.x, w3.x, ac3a); ac3b = fma2(hv.y, w3.y, ac3b);
        }

        float2 p0a = up2(ac0a), p0b = up2(ac0b);
        float2 p1a = up2(ac1a), p1b = up2(ac1b);
        float2 p2a = up2(ac2a), p2b = up2(ac2b);
        float2 p3a = up2(ac3a), p3b = up2(ac3b);
        float gi = (p0a.x + p0a.y) + (p0b.x + p0b.y) + gi0;
        float gf = (p1a.x + p1a.y) + (p1b.x + p1b.y) + gf0;
        float gg = (p2a.x + p2a.y) + (p2b.x + p2b.y) + gg0;
        float go = (p3a.x + p3a.y) + (p3b.x + p3b.y) + go0;

        float cn = sigm_f(gf) * creg + sigm_f(gi) * tanh_f(gg);
        float hn = sigm_f(go) * tanh_f(cn);

        bool m = xv > 0;
        if (jok)
            outp[((size_t)t * Bq + b) * (2 * Hq) + d * Hq + j] = m ? hn : 0.0f;
        if (m) { creg = cn; hreg = hn; }

        g_hbuf[((d * 2 + (pp ^ 1)) * Bq + b) * 512 + j] = hreg;
        gbar(cnt, GRPSZ * bs); bs++;
        pp ^= 1;
    }
}

// ---------------- output projection ----------------
__global__ __launch_bounds__(256) void k_outproj(const float* __restrict__ Wo,
                                                 const float* __restrict__ bo) {
    int r0 = blockIdx.x * 8;
    int tag = threadIdx.x & 31;
    int part = threadIdx.x >> 5;
    float acc[8];
#pragma unroll
    for (int r = 0; r < 8; r++) acc[r] = 0.0f;

    const float* w = Wo + (size_t)tag * 1000 + part * 125;
    for (int i = 0; i < 125; i++) {
        float wv = __ldg(&w[i]);
        int col = part * 125 + i;
#pragma unroll
        for (int r = 0; r < 8; r++)
            acc[r] = fmaf(wv, g_out1[(size_t)(r0 + r) * 1000 + col], acc[r]);
    }

    __shared__ float red[8][8][32];
#pragma unroll
    for (int r = 0; r < 8; r++) red[part][r][tag] = acc[r];
    __syncthreads();
    if (part == 0) {
#pragma unroll
        for (int r = 0; r < 8; r++) {
            float s = bo[tag];
#pragma unroll
            for (int p = 0; p < 8; p++) s += red[p][r][tag];
            g_y[(size_t)(r0 + r) * NT + tag] = s;
        }
    }
}

// ---------------- gold path score ----------------
__global__ void k_gold(const int* __restrict__ x, const int* __restrict__ y0,
                       const float* __restrict__ trans) {
    int b = blockIdx.x;
    float s = 0.0f;
    for (int t = threadIdx.x; t < Tq; t += blockDim.x) {
        if (x[b * Tq + t] > 0) {
            int cur = y0[b * Tq + t];
            int prev = (t == 0) ? 1 : y0[b * Tq + t - 1];
            s += g_y[((size_t)t * Bq + b) * NT + cur] + trans[cur * NT + prev];
        }
    }
    __shared__ float red[256];
    red[threadIdx.x] = s;
    __syncthreads();
    for (int k = 128; k > 0; k >>= 1) {
        if (threadIdx.x < k) red[threadIdx.x] += red[threadIdx.x + k];
        __syncthreads();
    }
    if (threadIdx.x == 0) g_gold[b] = red[0];
}

// ---------------- CRF forward ----------------
__global__ void k_crf(const int* __restrict__ x, const float* __restrict__ trans) {
    int b = blockIdx.x;
    int tag = threadIdx.x;
    __shared__ float st[NT * NT];
    __shared__ float ss[NT];
    for (int i = tag; i < NT * NT; i += 32) st[i] = trans[i];

    int len = 0;
    for (int t = tag; t < Tq; t += 32) len += (x[b * Tq + t] > 0) ? 1 : 0;
#pragma unroll
    for (int o = 16; o; o >>= 1) len += __shfl_xor_sync(0xffffffffu, len, o);

    float sc = (tag == 1) ? 0.0f : NEGV;
    ss[tag] = sc;
    __syncwarp();

    for (int t = 0; t < len; t++) {
        float emit = g_y[((size_t)t * Bq + b) * NT + tag];
        float mx = -3.4e38f;
#pragma unroll
        for (int p = 0; p < NT; p++) {
            float v = ss[p] + st[tag * NT + p];
            mx = fmaxf(mx, v);
        }
        float sum = 0.0f;
#pragma unroll
        for (int p = 0; p < NT; p++)
            sum += __expf(ss[p] + st[tag * NT + p] - mx);
        sc = emit + mx + __logf(sum);
        __syncwarp();
        ss[tag] = sc;
        __syncwarp();
    }

    float mx = sc;
#pragma unroll
    for (int o = 16; o; o >>= 1) mx = fmaxf(mx, __shfl_xor_sync(0xffffffffu, mx, o));
    float z;
    if (len < Tq) {
        z = mx + __logf(32.0f);
    } else {
        float sum = __expf(sc - mx);
#pragma unroll
        for (int o = 16; o; o >>= 1) sum += __shfl_xor_sync(0xffffffffu, sum, o);
        z = mx + __logf(sum);
    }
    if (tag == 0) g_Z[b] = z;
}

__global__ void k_final(float* __restrict__ out) {
    float s = 0.0f;
    for (int b = 0; b < Bq; b++) s += g_Z[b] - g_gold[b];
    out[0] = s / (float)Bq;
}

// ---------------- host launcher ----------------
extern "C" void kernel_launch(void* const* d_in, const int* in_sizes, int n_in,
                              void* d_out, int out_size) {
    (void)in_sizes; (void)n_in; (void)out_size;
    const int*   x     = (const int*)d_in[0];
    const int*   y0    = (const int*)d_in[1];
    const float* embw  = (const float*)d_in[2];
    const float* Wih0  = (const float*)d_in[3];
    const float* Whh0  = (const float*)d_in[4];
    const float* bih0  = (const float*)d_in[5];
    const float* bhh0  = (const float*)d_in[6];
    const float* Wih1  = (const float*)d_in[7];
    const float* Whh1  = (const float*)d_in[8];
    const float* bih1  = (const float*)d_in[9];
    const float* bhh1  = (const float*)d_in[10];
    const float* W_out = (const float*)d_in[11];
    const float* b_out = (const float*)d_in[12];
    const float* trans = (const float*)d_in[13];
    const float* h0    = (const float*)d_in[14];
    const float* c0    = (const float*)d_in[15];
    float* out = (float*)d_out;

    const int lstm_smem = (32000 + 4000) * sizeof(float);  // 144 KB
    cudaFuncSetAttribute(k_lstm, cudaFuncAttributeMaxDynamicSharedMemorySize, lstm_smem);

    k_embed<<<(Tq * Bq * Eq + 255) / 256, 256>>>(x, embw);

    {
        dim3 grid((G4 + 63) / 64, (Tq * Bq) / 64, 2);
        k_gemm<<<grid, 256>>>(0, Wih0, bih0, bhh0);
    }

    k_reset<<<1, 128>>>();
    k_lstm<<<NBLK, RTHR, lstm_smem>>>(0, Whh0, h0, c0, x);

    {
        dim3 grid((G4 + 63) / 64, (Tq * Bq) / 64, 2);
        k_gemm<<<grid, 256>>>(1, Wih1, bih1, bhh1);
    }

    k_reset<<<1, 128>>>();
    k_lstm<<<NBLK, RTHR, lstm_smem>>>(1, Whh1, h0, c0, x);

    k_outproj<<<(Tq * Bq) / 8, 256>>>(W_out, b_out);

    k_gold<<<Bq, 256>>>(x, y0, trans);
    k_crf<<<Bq, 32>>>(x, trans);
    k_final<<<1, 1>>>(out);
}

// round 6
// speedup vs baseline: 1.2872x; 1.0266x over previous
#include <cuda_runtime.h>
#include <math.h>
#include <stdint.h>

#define Bq 16
#define Tq 512
#define Eq 100
#define Hq 500
#define G4 2000
#define NT 32
#define NEGV (-10000.0f)

#define NBLK 128
#define RTHR 256
#define GRPSZ 32

typedef unsigned long long ull;

// ---------------- device scratch ----------------
__device__ float g_xs[Tq * Bq * Eq];
__device__ float g_A0[2u * Tq * Bq * G4];
__device__ float g_A1[2u * Tq * Bq * G4];
__device__ float g_out0[Tq * Bq * 2 * Hq];
__device__ float g_out1[Tq * Bq * 2 * Hq];
__device__ float g_y[Tq * Bq * NT];
__device__ float g_hbuf[2 * 2 * Bq * 512];   // [d][pp][b][512]
__device__ float g_gold[Bq];
__device__ float g_Z[Bq];
__device__ unsigned g_cnt[4 * 32];           // per-group counters, 128B apart

// ---------------- helpers ----------------
__device__ __forceinline__ float sigm_f(float v) {
    return __fdividef(1.0f, 1.0f + __expf(-v));
}
__device__ __forceinline__ float tanh_f(float v) {
    return 1.0f - __fdividef(2.0f, __expf(2.0f * v) + 1.0f);
}
__device__ __forceinline__ ull fma2(ull a, ull b, ull c) {
    ull d;
    asm("fma.rn.f32x2 %0, %1, %2, %3;" : "=l"(d) : "l"(a), "l"(b), "l"(c));
    return d;
}
__device__ __forceinline__ ull pk2(float a, float b) {
    ull r;
    asm("mov.b64 %0, {%1, %2};" : "=l"(r) : "f"(a), "f"(b));
    return r;
}
__device__ __forceinline__ float2 up2(ull v) {
    float2 r;
    asm("mov.b64 {%0, %1}, %2;" : "=f"(r.x), "=f"(r.y) : "l"(v));
    return r;
}
__device__ __forceinline__ void red_release_add1(unsigned* p) {
    asm volatile("red.release.gpu.global.add.u32 [%0], 1;" :: "l"(p) : "memory");
}
__device__ __forceinline__ unsigned ld_acquire(const unsigned* p) {
    unsigned v;
    asm volatile("ld.acquire.gpu.global.u32 %0, [%1];" : "=r"(v) : "l"(p) : "memory");
    return v;
}

__global__ void k_reset() {
    if (threadIdx.x < 4 * 32) g_cnt[threadIdx.x] = 0u;
}

// ---------------- embedding ----------------
__global__ void k_embed(const int* __restrict__ x, const float* __restrict__ embw) {
    int idx = blockIdx.x * blockDim.x + threadIdx.x;
    if (idx >= Tq * Bq * Eq) return;
    int e = idx % Eq;
    int rb = idx / Eq;
    int b = rb % Bq;
    int t = rb / Bq;
    int row = x[b * Tq + t];
    g_xs[idx] = embw[(size_t)row * Eq + e];
}

// ---------------- tiled fp32 GEMM, FFMA2, double-buffered smem ----------------
__global__ __launch_bounds__(256) void k_gemm(int lay,
                                              const float* __restrict__ W,
                                              const float* __restrict__ b1,
                                              const float* __restrict__ b2) {
    const int M = Tq * Bq;
    const int N = G4;
    const int K = (lay == 0) ? Eq : (2 * Hq);
    const float* X = (lay == 0) ? g_xs : g_out0;
    float* C = (lay == 0) ? g_A0 : g_A1;

    __shared__ ull sXp[2][8][64];
    __shared__ ull sWp[2][8][64];

    int d = blockIdx.z;
    const float* Wd = W + (size_t)d * N * K;
    const float* b1d = b1 + (size_t)d * N;
    const float* b2d = b2 + (size_t)d * N;
    float* Cd = C + (size_t)d * M * N;

    int m0 = blockIdx.y * 64, n0 = blockIdx.x * 64;
    int tid = threadIdx.x;
    int lr = tid >> 2;
    int lc = (tid & 3) * 4;
    int tx = tid & 15, ty = tid >> 4;

    ull acc2[4][4];
#pragma unroll
    for (int i = 0; i < 4; i++)
#pragma unroll
        for (int j = 0; j < 4; j++) acc2[i][j] = 0ull;

    const int nt = (K + 15) / 16;

    // prologue: tile 0
    float4 xv = make_float4(0.f, 0.f, 0.f, 0.f);
    float4 wv = make_float4(0.f, 0.f, 0.f, 0.f);
    if (lc < K) xv = *(const float4*)&X[(size_t)(m0 + lr) * K + lc];
    if (lc < K) wv = *(const float4*)&Wd[(size_t)(n0 + lr) * K + lc];
    sXp[0][(lc >> 1) + 0][lr] = pk2(xv.x, xv.y);
    sXp[0][(lc >> 1) + 1][lr] = pk2(xv.z, xv.w);
    sWp[0][(lc >> 1) + 0][lr] = pk2(wv.x, wv.y);
    sWp[0][(lc >> 1) + 1][lr] = pk2(wv.z, wv.w);
    __syncthreads();

    for (int ti = 0; ti < nt; ti++) {
        int cur = ti & 1;
        // prefetch next tile (global -> regs), overlapped with compute
        float4 xn = make_float4(0.f, 0.f, 0.f, 0.f);
        float4 wn = make_float4(0.f, 0.f, 0.f, 0.f);
        if (ti + 1 < nt) {
            int kt = (ti + 1) * 16;
            if (kt + lc < K) xn = *(const float4*)&X[(size_t)(m0 + lr) * K + kt + lc];
            if (kt + lc < K) wn = *(const float4*)&Wd[(size_t)(n0 + lr) * K + kt + lc];
        }
#pragma unroll
        for (int kp = 0; kp < 8; kp++) {
            ulonglong2 xa = *(const ulonglong2*)&sXp[cur][kp][ty * 4 + 0];
            ulonglong2 xb = *(const ulonglong2*)&sXp[cur][kp][ty * 4 + 2];
            ulonglong2 wa = *(const ulonglong2*)&sWp[cur][kp][tx * 4 + 0];
            ulonglong2 wb = *(const ulonglong2*)&sWp[cur][kp][tx * 4 + 2];
            ull xp[4] = {xa.x, xa.y, xb.x, xb.y};
            ull wp[4] = {wa.x, wa.y, wb.x, wb.y};
#pragma unroll
            for (int i = 0; i < 4; i++)
#pragma unroll
                for (int j = 0; j < 4; j++)
                    acc2[i][j] = fma2(xp[i], wp[j], acc2[i][j]);
        }
        if (ti + 1 < nt) {
            int nxt = (ti + 1) & 1;
            sXp[nxt][(lc >> 1) + 0][lr] = pk2(xn.x, xn.y);
            sXp[nxt][(lc >> 1) + 1][lr] = pk2(xn.z, xn.w);
            sWp[nxt][(lc >> 1) + 0][lr] = pk2(wn.x, wn.y);
            sWp[nxt][(lc >> 1) + 1][lr] = pk2(wn.z, wn.w);
            __syncthreads();
        }
    }

#pragma unroll
    for (int i = 0; i < 4; i++) {
        int row = m0 + ty * 4 + i;
#pragma unroll
        for (int j = 0; j < 4; j++) {
            int col = n0 + tx * 4 + j;
            if (col < N) {
                float2 p = up2(acc2[i][j]);
                Cd[(size_t)row * N + col] = p.x + p.y + b1d[col] + b2d[col];
            }
        }
    }
}

// ---------------- persistent bidirectional LSTM ----------------
// 128 blocks = (2 dirs) x (2 b-groups of 8) x (32 j-groups of 16).
// 256 threads: bl = tid&7, jl = (tid>>3)&15, ks = tid>>7 (2-way K-split of the dot).
__device__ __forceinline__ void gbar_all(unsigned* cnt, unsigned want) {
    __syncthreads();                  // all block work for this step done
    if (threadIdx.x == 0) red_release_add1(cnt);
    int spins = 0;
    while (ld_acquire(cnt) < want) {
        if (++spins > 64) __nanosleep(30);
    }
    // every thread holds its own acquire; no trailing syncthreads needed
}

__global__ __launch_bounds__(RTHR, 1) void k_lstm(int lay,
                                                  const float* __restrict__ Whh,
                                                  const float* __restrict__ h0,
                                                  const float* __restrict__ c0,
                                                  const int* __restrict__ x) {
    extern __shared__ float sm[];
    float* sW = sm;            // [g][jl][i] : 4*16*500 = 32000 floats (128 KB)
    float* sh = sm + 32000;    // [bl][i]    : 8*500    = 4000 floats  (16 KB)
    float* sred = sm + 36000;  // [tid][4]   : 256*4    = 1024 floats  (4 KB)

    const float* A = (lay == 0) ? g_A0 : g_A1;
    float* outp = (lay == 0) ? g_out0 : g_out1;
    const int hbase = lay * 2;

    int tid = threadIdx.x;
    int bl = tid & 7;
    int jl = (tid >> 3) & 15;
    int ks = tid >> 7;          // 0 or 1
    int bx = blockIdx.x;
    int d = bx >> 6;
    int rem = bx & 63;
    int bg = rem >> 5;
    int jg = rem & 31;
    int b0 = bg * 8;
    int j0 = jg * 16;
    int j = j0 + jl;
    int b = b0 + bl;
    bool jok = (j < Hq);
    unsigned* cnt = &g_cnt[(d * 2 + bg) * 32];

    // load Whh slice: sW[(g*16+jl2)*500 + i]
    for (int idx = tid; idx < 32000; idx += RTHR) {
        int g = idx / 8000;
        int r = idx % 8000;
        int jl2 = r / 500;
        int i = r % 500;
        int jc = j0 + jl2;
        sW[idx] = (jc < Hq) ? Whh[((size_t)d * G4 + g * Hq + jc) * Hq + i] : 0.0f;
    }

    float hreg = 0.0f, creg = 0.0f;
    if (ks == 0) {
        hreg = jok ? h0[((size_t)(hbase + d) * Bq + b) * Hq + j] : 0.0f;
        creg = jok ? c0[((size_t)(hbase + d) * Bq + b) * Hq + j] : 0.0f;
        g_hbuf[((d * 2 + 0) * Bq + b) * 512 + j] = hreg;
    }
    unsigned bs = 1;
    gbar_all(cnt, GRPSZ * bs); bs++;

    const float* Ad = A + (size_t)d * Tq * Bq * G4;
    const ulonglong2* w0p = (const ulonglong2*)&sW[(0 * 16 + jl) * 500];
    const ulonglong2* w1p = (const ulonglong2*)&sW[(1 * 16 + jl) * 500];
    const ulonglong2* w2p = (const ulonglong2*)&sW[(2 * 16 + jl) * 500];
    const ulonglong2* w3p = (const ulonglong2*)&sW[(3 * 16 + jl) * 500];
    const int i0 = ks * 63;
    const int i1 = ks ? 125 : 63;

    int pp = 0;
    for (int s = 0; s < Tq; s++) {
        int t = d ? (Tq - 1 - s) : s;
        // each ks-half prefetches two gate pre-activations
        size_t arow = ((size_t)t * Bq + b) * G4 + (jok ? j : 0);
        float ag0 = __ldg(&Ad[arow + (size_t)(2 * ks + 0) * Hq]);
        float ag1 = __ldg(&Ad[arow + (size_t)(2 * ks + 1) * Hq]);
        int xv = (ks == 0) ? __ldg(&x[b * Tq + t]) : 0;

        // stage h for this block's 8 batch rows: 1000 float4 over 256 threads
        for (int q = tid; q < 1000; q += RTHR) {
            int bb = q / 125;
            int i4 = q % 125;
            float4 v = __ldcg((const float4*)&g_hbuf[((d * 2 + pp) * Bq + b0 + bb) * 512 + i4 * 4]);
            *(float4*)&sh[bb * 500 + i4 * 4] = v;
        }
        __syncthreads();

        const ulonglong2* hp = (const ulonglong2*)&sh[bl * 500];
        ull ac0a = 0ull, ac0b = 0ull, ac1a = 0ull, ac1b = 0ull;
        ull ac2a = 0ull, ac2b = 0ull, ac3a = 0ull, ac3b = 0ull;
#pragma unroll 3
        for (int ii = i0; ii < i1; ii++) {
            ulonglong2 hv = hp[ii];
            ulonglong2 w0 = w0p[ii], w1 = w1p[ii], w2 = w2p[ii], w3 = w3p[ii];
            ac0a = fma2(hv.x, w0.x, ac0a); ac0b = fma2(hv.y, w0.y, ac0b);
            ac1a = fma2(hv.x, w1.x, ac1a); ac1b = fma2(hv.y, w1.y, ac1b);
            ac2a = fma2(hv.x, w2.x, ac2a); ac2b = fma2(hv.y, w2.y, ac2b);
            ac3a = fma2(hv.x, w3.x, ac3a); ac3b = fma2(hv.y, w3.y, ac3b);
        }

        float2 p0a = up2(ac0a), p0b = up2(ac0b);
        float2 p1a = up2(ac1a), p1b = up2(ac1b);
        float2 p2a = up2(ac2a), p2b = up2(ac2b);
        float2 p3a = up2(ac3a), p3b = up2(ac3b);
        float p0 = (p0a.x + p0a.y) + (p0b.x + p0b.y);
        float p1 = (p1a.x + p1a.y) + (p1b.x + p1b.y);
        float p2 = (p2a.x + p2a.y) + (p2b.x + p2b.y);
        float p3 = (p3a.x + p3a.y) + (p3b.x + p3b.y);
        // fold A-loads into this half's partials (ks0 -> gates 0,1; ks1 -> gates 2,3)
        if (ks == 0) { p0 += ag0; p1 += ag1; }
        else         { p2 += ag0; p3 += ag1; }
        *(float4*)&sred[tid * 4] = make_float4(p0, p1, p2, p3);
        __syncthreads();

        if (ks == 0) {
            float4 mine = *(const float4*)&sred[tid * 4];
            float4 peer = *(const float4*)&sred[(tid + 128) * 4];
            float gi = mine.x + peer.x;
            float gf = mine.y + peer.y;
            float gg = mine.z + peer.z;
            float go = mine.w + peer.w;

            float cn = sigm_f(gf) * creg + sigm_f(gi) * tanh_f(gg);
            float hn = sigm_f(go) * tanh_f(cn);

            bool m = xv > 0;
            if (jok)
                outp[((size_t)t * Bq + b) * (2 * Hq) + d * Hq + j] = m ? hn : 0.0f;
            if (m) { creg = cn; hreg = hn; }

            g_hbuf[((d * 2 + (pp ^ 1)) * Bq + b) * 512 + j] = hreg;
        }
        gbar_all(cnt, GRPSZ * bs); bs++;
        pp ^= 1;
    }
}

// ---------------- output projection ----------------
__global__ __launch_bounds__(256) void k_outproj(const float* __restrict__ Wo,
                                                 const float* __restrict__ bo) {
    int r0 = blockIdx.x * 8;
    int tag = threadIdx.x & 31;
    int part = threadIdx.x >> 5;
    float acc[8];
#pragma unroll
    for (int r = 0; r < 8; r++) acc[r] = 0.0f;

    const float* w = Wo + (size_t)tag * 1000 + part * 125;
    for (int i = 0; i < 125; i++) {
        float wv = __ldg(&w[i]);
        int col = part * 125 + i;
#pragma unroll
        for (int r = 0; r < 8; r++)
            acc[r] = fmaf(wv, g_out1[(size_t)(r0 + r) * 1000 + col], acc[r]);
    }

    __shared__ float red[8][8][32];
#pragma unroll
    for (int r = 0; r < 8; r++) red[part][r][tag] = acc[r];
    __syncthreads();
    if (part == 0) {
#pragma unroll
        for (int r = 0; r < 8; r++) {
            float s = bo[tag];
#pragma unroll
            for (int p = 0; p < 8; p++) s += red[p][r][tag];
            g_y[(size_t)(r0 + r) * NT + tag] = s;
        }
    }
}

// ---------------- gold path score ----------------
__global__ void k_gold(const int* __restrict__ x, const int* __restrict__ y0,
                       const float* __restrict__ trans) {
    int b = blockIdx.x;
    float s = 0.0f;
    for (int t = threadIdx.x; t < Tq; t += blockDim.x) {
        if (x[b * Tq + t] > 0) {
            int cur = y0[b * Tq + t];
            int prev = (t == 0) ? 1 : y0[b * Tq + t - 1];
            s += g_y[((size_t)t * Bq + b) * NT + cur] + trans[cur * NT + prev];
        }
    }
    __shared__ float red[256];
    red[threadIdx.x] = s;
    __syncthreads();
    for (int k = 128; k > 0; k >>= 1) {
        if (threadIdx.x < k) red[threadIdx.x] += red[threadIdx.x + k];
        __syncthreads();
    }
    if (threadIdx.x == 0) g_gold[b] = red[0];
}

// ---------------- CRF forward ----------------
__global__ void k_crf(const int* __restrict__ x, const float* __restrict__ trans) {
    int b = blockIdx.x;
    int tag = threadIdx.x;
    __shared__ float st[NT * NT];
    __shared__ float ss[NT];
    for (int i = tag; i < NT * NT; i += 32) st[i] = trans[i];

    int len = 0;
    for (int t = tag; t < Tq; t += 32) len += (x[b * Tq + t] > 0) ? 1 : 0;
#pragma unroll
    for (int o = 16; o; o >>= 1) len += __shfl_xor_sync(0xffffffffu, len, o);

    float sc = (tag == 1) ? 0.0f : NEGV;
    ss[tag] = sc;
    __syncwarp();

    for (int t = 0; t < len; t++) {
        float emit = g_y[((size_t)t * Bq + b) * NT + tag];
        float mx = -3.4e38f;
#pragma unroll
        for (int p = 0; p < NT; p++) {
            float v = ss[p] + st[tag * NT + p];
            mx = fmaxf(mx, v);
        }
        float sum = 0.0f;
#pragma unroll
        for (int p = 0; p < NT; p++)
            sum += __expf(ss[p] + st[tag * NT + p] - mx);
        sc = emit + mx + __logf(sum);
        __syncwarp();
        ss[tag] = sc;
        __syncwarp();
    }

    float mx = sc;
#pragma unroll
    for (int o = 16; o; o >>= 1) mx = fmaxf(mx, __shfl_xor_sync(0xffffffffu, mx, o));
    float z;
    if (len < Tq) {
        z = mx + __logf(32.0f);
    } else {
        float sum = __expf(sc - mx);
#pragma unroll
        for (int o = 16; o; o >>= 1) sum += __shfl_xor_sync(0xffffffffu, sum, o);
        z = mx + __logf(sum);
    }
    if (tag == 0) g_Z[b] = z;
}

__global__ void k_final(float* __restrict__ out) {
    float s = 0.0f;
    for (int b = 0; b < Bq; b++) s += g_Z[b] - g_gold[b];
    out[0] = s / (float)Bq;
}

// ---------------- host launcher ----------------
extern "C" void kernel_launch(void* const* d_in, const int* in_sizes, int n_in,
                              void* d_out, int out_size) {
    (void)in_sizes; (void)n_in; (void)out_size;
    const int*   x     = (const int*)d_in[0];
    const int*   y0    = (const int*)d_in[1];
    const float* embw  = (const float*)d_in[2];
    const float* Wih0  = (const float*)d_in[3];
    const float* Whh0  = (const float*)d_in[4];
    const float* bih0  = (const float*)d_in[5];
    const float* bhh0  = (const float*)d_in[6];
    const float* Wih1  = (const float*)d_in[7];
    const float* Whh1  = (const float*)d_in[8];
    const float* bih1  = (const float*)d_in[9];
    const float* bhh1  = (const float*)d_in[10];
    const float* W_out = (const float*)d_in[11];
    const float* b_out = (const float*)d_in[12];
    const float* trans = (const float*)d_in[13];
    const float* h0    = (const float*)d_in[14];
    const float* c0    = (const float*)d_in[15];
    float* out = (float*)d_out;

    const int lstm_smem = (32000 + 4000 + 1024) * sizeof(float);  // 148 KB
    cudaFuncSetAttribute(k_lstm, cudaFuncAttributeMaxDynamicSharedMemorySize, lstm_smem);

    k_embed<<<(Tq * Bq * Eq + 255) / 256, 256>>>(x, embw);

    {
        dim3 grid((G4 + 63) / 64, (Tq * Bq) / 64, 2);
        k_gemm<<<grid, 256>>>(0, Wih0, bih0, bhh0);
    }

    k_reset<<<1, 128>>>();
    k_lstm<<<NBLK, RTHR, lstm_smem>>>(0, Whh0, h0, c0, x);

    {
        dim3 grid((G4 + 63) / 64, (Tq * Bq) / 64, 2);
        k_gemm<<<grid, 256>>>(1, Wih1, bih1, bhh1);
    }

    k_reset<<<1, 128>>>();
    k_lstm<<<NBLK, RTHR, lstm_smem>>>(1, Whh1, h0, c0, x);

    k_outproj<<<(Tq * Bq) / 8, 256>>>(W_out, b_out);

    k_gold<<<Bq, 256>>>(x, y0, trans);
    k_crf<<<Bq, 32>>>(x, trans);
    k_final<<<1, 1>>>(out);
}

// round 11
// speedup vs baseline: 1.4697x; 1.1418x over previous
#include <cuda_runtime.h>
#include <math.h>
#include <stdint.h>

#define Bq 16
#define Tq 512
#define Eq 100
#define Hq 500
#define G4 2000
#define NT 32
#define NEGV (-10000.0f)

#define NBLK 128
#define RTHR 128
#define GRPSZ 32

// sred padded strides (floats)
#define SR_B 68
#define SR_KS 548

typedef unsigned long long ull;

// ---------------- device scratch ----------------
__device__ float g_xs[Tq * Bq * Eq];
__device__ float g_A0[2u * Tq * Bq * G4];
__device__ float g_A1[2u * Tq * Bq * G4];
__device__ float g_out0[Tq * Bq * 2 * Hq];
__device__ float g_out1[Tq * Bq * 2 * Hq];
__device__ float g_y[Tq * Bq * NT];
__device__ float g_hbuf[2 * 2 * Bq * 512];   // [d][pp][b][512]
__device__ float g_gold[Bq];
__device__ float g_Z[Bq];
__device__ unsigned g_cnt[4 * 32];           // per-group counters, 128B apart

// ---------------- helpers ----------------
__device__ __forceinline__ float sigm_f(float v) {
    return __fdividef(1.0f, 1.0f + __expf(-v));
}
__device__ __forceinline__ float tanh_f(float v) {
    return 1.0f - __fdividef(2.0f, __expf(2.0f * v) + 1.0f);
}
__device__ __forceinline__ ull fma2(ull a, ull b, ull c) {
    ull d;
    asm("fma.rn.f32x2 %0, %1, %2, %3;" : "=l"(d) : "l"(a), "l"(b), "l"(c));
    return d;
}
__device__ __forceinline__ ull pk2(float a, float b) {
    ull r;
    asm("mov.b64 %0, {%1, %2};" : "=l"(r) : "f"(a), "f"(b));
    return r;
}
__device__ __forceinline__ float2 up2(ull v) {
    float2 r;
    asm("mov.b64 {%0, %1}, %2;" : "=f"(r.x), "=f"(r.y) : "l"(v));
    return r;
}
__device__ __forceinline__ void red_release_add1(unsigned* p) {
    asm volatile("red.release.gpu.global.add.u32 [%0], 1;" :: "l"(p) : "memory");
}
__device__ __forceinline__ unsigned ld_acquire(const unsigned* p) {
    unsigned v;
    asm volatile("ld.acquire.gpu.global.u32 %0, [%1];" : "=r"(v) : "l"(p) : "memory");
    return v;
}

__global__ void k_reset() {
    if (threadIdx.x < 4 * 32) g_cnt[threadIdx.x] = 0u;
}

// ---------------- embedding ----------------
__global__ void k_embed(const int* __restrict__ x, const float* __restrict__ embw) {
    int idx = blockIdx.x * blockDim.x + threadIdx.x;
    if (idx >= Tq * Bq * Eq) return;
    int e = idx % Eq;
    int rb = idx / Eq;
    int b = rb % Bq;
    int t = rb / Bq;
    int row = x[b * Tq + t];
    g_xs[idx] = embw[(size_t)row * Eq + e];
}

// ---------------- tiled fp32 GEMM, FFMA2, double-buffered smem ----------------
__global__ __launch_bounds__(256) void k_gemm(int lay,
                                              const float* __restrict__ W,
                                              const float* __restrict__ b1,
                                              const float* __restrict__ b2) {
    const int M = Tq * Bq;
    const int N = G4;
    const int K = (lay == 0) ? Eq : (2 * Hq);
    const float* X = (lay == 0) ? g_xs : g_out0;
    float* C = (lay == 0) ? g_A0 : g_A1;

    __shared__ ull sXp[2][8][64];
    __shared__ ull sWp[2][8][64];

    int d = blockIdx.z;
    const float* Wd = W + (size_t)d * N * K;
    const float* b1d = b1 + (size_t)d * N;
    const float* b2d = b2 + (size_t)d * N;
    float* Cd = C + (size_t)d * M * N;

    int m0 = blockIdx.y * 64, n0 = blockIdx.x * 64;
    int tid = threadIdx.x;
    int lr = tid >> 2;
    int lc = (tid & 3) * 4;
    int tx = tid & 15, ty = tid >> 4;

    ull acc2[4][4];
#pragma unroll
    for (int i = 0; i < 4; i++)
#pragma unroll
        for (int j = 0; j < 4; j++) acc2[i][j] = 0ull;

    const int nt = (K + 15) / 16;

    float4 xv = make_float4(0.f, 0.f, 0.f, 0.f);
    float4 wv = make_float4(0.f, 0.f, 0.f, 0.f);
    if (lc < K) xv = *(const float4*)&X[(size_t)(m0 + lr) * K + lc];
    if (lc < K) wv = *(const float4*)&Wd[(size_t)(n0 + lr) * K + lc];
    sXp[0][(lc >> 1) + 0][lr] = pk2(xv.x, xv.y);
    sXp[0][(lc >> 1) + 1][lr] = pk2(xv.z, xv.w);
    sWp[0][(lc >> 1) + 0][lr] = pk2(wv.x, wv.y);
    sWp[0][(lc >> 1) + 1][lr] = pk2(wv.z, wv.w);
    __syncthreads();

    for (int ti = 0; ti < nt; ti++) {
        int cur = ti & 1;
        float4 xn = make_float4(0.f, 0.f, 0.f, 0.f);
        float4 wn = make_float4(0.f, 0.f, 0.f, 0.f);
        if (ti + 1 < nt) {
            int kt = (ti + 1) * 16;
            if (kt + lc < K) xn = *(const float4*)&X[(size_t)(m0 + lr) * K + kt + lc];
            if (kt + lc < K) wn = *(const float4*)&Wd[(size_t)(n0 + lr) * K + kt + lc];
        }
#pragma unroll
        for (int kp = 0; kp < 8; kp++) {
            ulonglong2 xa = *(const ulonglong2*)&sXp[cur][kp][ty * 4 + 0];
            ulonglong2 xb = *(const ulonglong2*)&sXp[cur][kp][ty * 4 + 2];
            ulonglong2 wa = *(const ulonglong2*)&sWp[cur][kp][tx * 4 + 0];
            ulonglong2 wb = *(const ulonglong2*)&sWp[cur][kp][tx * 4 + 2];
            ull xp[4] = {xa.x, xa.y, xb.x, xb.y};
            ull wp[4] = {wa.x, wa.y, wb.x, wb.y};
#pragma unroll
            for (int i = 0; i < 4; i++)
#pragma unroll
                for (int j = 0; j < 4; j++)
                    acc2[i][j] = fma2(xp[i], wp[j], acc2[i][j]);
        }
        if (ti + 1 < nt) {
            int nxt = (ti + 1) & 1;
            sXp[nxt][(lc >> 1) + 0][lr] = pk2(xn.x, xn.y);
            sXp[nxt][(lc >> 1) + 1][lr] = pk2(xn.z, xn.w);
            sWp[nxt][(lc >> 1) + 0][lr] = pk2(wn.x, wn.y);
            sWp[nxt][(lc >> 1) + 1][lr] = pk2(wn.z, wn.w);
            __syncthreads();
        }
    }

#pragma unroll
    for (int i = 0; i < 4; i++) {
        int row = m0 + ty * 4 + i;
#pragma unroll
        for (int j = 0; j < 4; j++) {
            int col = n0 + tx * 4 + j;
            if (col < N) {
                float2 p = up2(acc2[i][j]);
                Cd[(size_t)row * N + col] = p.x + p.y + b1d[col] + b2d[col];
            }
        }
    }
}

// ---------------- persistent bidirectional LSTM, register-tiled ----------------
// 128 blocks = (2 dirs) x (2 b-groups of 8) x (32 j-groups of 16).
// 128 threads = 8 K-splits x (2 b-subgroups x 8 j-subgroups).
// Dot thread computes 4 batch x 2 j x 4 gates over its K-slice.
__device__ __forceinline__ void gbar_all(unsigned* cnt, unsigned want) {
    __syncthreads();
    if (threadIdx.x == 0) red_release_add1(cnt);
    unsigned ns = 20;
    while (ld_acquire(cnt) < want) {
        __nanosleep(ns);
        if (ns < 160) ns += ns;   // gentle exponential backoff
    }
}

__global__ __launch_bounds__(RTHR, 1) void k_lstm(int lay,
                                                  const float* __restrict__ Whh,
                                                  const float* __restrict__ h0,
                                                  const float* __restrict__ c0,
                                                  const int* __restrict__ x) {
    extern __shared__ float sm[];
    float* sW = sm;            // [g][jl][i] : 4*16*500 = 32000 floats (128 KB)
    float* sh = sm + 32000;    // [bl][i]    : 8*500    = 4000 floats  (16 KB)
    float* sred = sm + 36000;  // [ks][b][j][g] padded : 8*548 = 4384 floats

    const float* A = (lay == 0) ? g_A0 : g_A1;
    float* outp = (lay == 0) ? g_out0 : g_out1;
    const int hbase = lay * 2;

    int tid = threadIdx.x;
    // dot role
    int ks = tid >> 4;          // 0..7
    int cell = tid & 15;
    int bg_t = cell & 1;        // 0..1 : batches bg_t*4 .. +3
    int jg_t = cell >> 1;       // 0..7 : j pair jg_t*2, jg_t*2+1
    // owner role
    int obl = tid & 7;          // batch 0..7
    int ojl = tid >> 3;         // j 0..15

    int bx = blockIdx.x;
    int d = bx >> 6;
    int rem = bx & 63;
    int bg = rem >> 5;
    int jg = rem & 31;
    int b0 = bg * 8;
    int j0 = jg * 16;
    int oj = j0 + ojl;
    int ob = b0 + obl;
    bool jok = (oj < Hq);
    unsigned* cnt = &g_cnt[(d * 2 + bg) * 32];

    // load Whh slice: sW[(g*16+jl2)*500 + i]
    for (int idx = tid; idx < 32000; idx += RTHR) {
        int g = idx / 8000;
        int r = idx % 8000;
        int jl2 = r / 500;
        int i = r % 500;
        int jc = j0 + jl2;
        sW[idx] = (jc < Hq) ? Whh[((size_t)d * G4 + g * Hq + jc) * Hq + i] : 0.0f;
    }

    float hreg = jok ? h0[((size_t)(hbase + d) * Bq + ob) * Hq + oj] : 0.0f;
    float creg = jok ? c0[((size_t)(hbase + d) * Bq + ob) * Hq + oj] : 0.0f;
    g_hbuf[((d * 2 + 0) * Bq + ob) * 512 + oj] = hreg;
    unsigned bs = 1;
    gbar_all(cnt, GRPSZ * bs); bs++;

    const float* Ad = A + (size_t)d * Tq * Bq * G4;

    // K-slice for this thread: chunks of 4 floats (ulonglong2), 125 total
    int cb = ks * 15 + (ks < 5 ? ks : 5);
    int cn = (ks < 5) ? 16 : 15;

    // smem row pointers
    const ulonglong2* hrow[4];
#pragma unroll
    for (int bi = 0; bi < 4; bi++)
        hrow[bi] = (const ulonglong2*)&sh[(bg_t * 4 + bi) * 500];
    const ulonglong2* wrow[2][4];
#pragma unroll
    for (int ji = 0; ji < 2; ji++)
#pragma unroll
        for (int g = 0; g < 4; g++)
            wrow[ji][g] = (const ulonglong2*)&sW[(g * 16 + jg_t * 2 + ji) * 500];

    int pp = 0;
    for (int s = 0; s < Tq; s++) {
        int t = d ? (Tq - 1 - s) : s;
        // owner prefetch: gate pre-activations + mask
        size_t arow = ((size_t)t * Bq + ob) * G4 + (jok ? oj : 0);
        float ag0 = __ldg(&Ad[arow + 0 * Hq]);
        float ag1 = __ldg(&Ad[arow + 1 * Hq]);
        float ag2 = __ldg(&Ad[arow + 2 * Hq]);
        float ag3 = __ldg(&Ad[arow + 3 * Hq]);
        int xv = __ldg(&x[ob * Tq + t]);

        // stage h for this block's 8 batch rows: exactly 8*125 = 1000 float4
        for (int q = tid; q < 1000; q += RTHR) {
            int bb = q / 125;              // 0..7  (FIXED: full coverage)
            int i4 = q - bb * 125;         // 0..124
            float4 v = __ldcg((const float4*)&g_hbuf[((d * 2 + pp) * Bq + b0 + bb) * 512 + i4 * 4]);
            *(float4*)&sh[bb * 500 + i4 * 4] = v;
        }
        __syncthreads();

        // register-tiled dot: acc[bi][ji][g]
        ull acc[4][2][4];
#pragma unroll
        for (int bi = 0; bi < 4; bi++)
#pragma unroll
            for (int ji = 0; ji < 2; ji++)
#pragma unroll
                for (int g = 0; g < 4; g++) acc[bi][ji][g] = 0ull;

#pragma unroll 2
        for (int ii = cb; ii < cb + cn; ii++) {
            ulonglong2 hv[4];
#pragma unroll
            for (int bi = 0; bi < 4; bi++) hv[bi] = hrow[bi][ii];
            ulonglong2 wv[2][4];
#pragma unroll
            for (int ji = 0; ji < 2; ji++)
#pragma unroll
                for (int g = 0; g < 4; g++) wv[ji][g] = wrow[ji][g][ii];
#pragma unroll
            for (int bi = 0; bi < 4; bi++)
#pragma unroll
                for (int ji = 0; ji < 2; ji++)
#pragma unroll
                    for (int g = 0; g < 4; g++) {
                        acc[bi][ji][g] = fma2(hv[bi].x, wv[ji][g].x, acc[bi][ji][g]);
                        acc[bi][ji][g] = fma2(hv[bi].y, wv[ji][g].y, acc[bi][ji][g]);
                    }
        }

        // write partials to sred[ks][b][j][g] (padded)
#pragma unroll
        for (int bi = 0; bi < 4; bi++)
#pragma unroll
            for (int ji = 0; ji < 2; ji++)
#pragma unroll
                for (int g = 0; g < 4; g++) {
                    float2 p = up2(acc[bi][ji][g]);
                    sred[ks * SR_KS + (bg_t * 4 + bi) * SR_B + (jg_t * 2 + ji) * 4 + g] = p.x + p.y;
                }
        __syncthreads();

        // owner: reduce 8 K-partials per gate, nonlinearity, state update
        {
            int base = obl * SR_B + ojl * 4;
            float gi = ag0, gf = ag1, gg = ag2, go = ag3;
#pragma unroll
            for (int k = 0; k < 8; k++) {
                const float* r = &sred[k * SR_KS + base];
                gi += r[0]; gf += r[1]; gg += r[2]; go += r[3];
            }

            float cn2 = sigm_f(gf) * creg + sigm_f(gi) * tanh_f(gg);
            float hn = sigm_f(go) * tanh_f(cn2);

            bool m = xv > 0;
            if (jok)
                outp[((size_t)t * Bq + ob) * (2 * Hq) + d * Hq + oj] = m ? hn : 0.0f;
            if (m) { creg = cn2; hreg = hn; }

            g_hbuf[((d * 2 + (pp ^ 1)) * Bq + ob) * 512 + oj] = hreg;
        }
        gbar_all(cnt, GRPSZ * bs); bs++;
        pp ^= 1;
    }
}

// ---------------- output projection ----------------
__global__ __launch_bounds__(256) void k_outproj(const float* __restrict__ Wo,
                                                 const float* __restrict__ bo) {
    int r0 = blockIdx.x * 8;
    int tag = threadIdx.x & 31;
    int part = threadIdx.x >> 5;
    float acc[8];
#pragma unroll
    for (int r = 0; r < 8; r++) acc[r] = 0.0f;

    const float* w = Wo + (size_t)tag * 1000 + part * 125;
    for (int i = 0; i < 125; i++) {
        float wv = __ldg(&w[i]);
        int col = part * 125 + i;
#pragma unroll
        for (int r = 0; r < 8; r++)
            acc[r] = fmaf(wv, g_out1[(size_t)(r0 + r) * 1000 + col], acc[r]);
    }

    __shared__ float red[8][8][32];
#pragma unroll
    for (int r = 0; r < 8; r++) red[part][r][tag] = acc[r];
    __syncthreads();
    if (part == 0) {
#pragma unroll
        for (int r = 0; r < 8; r++) {
            float s = bo[tag];
#pragma unroll
            for (int p = 0; p < 8; p++) s += red[p][r][tag];
            g_y[(size_t)(r0 + r) * NT + tag] = s;
        }
    }
}

// ---------------- gold path score ----------------
__global__ void k_gold(const int* __restrict__ x, const int* __restrict__ y0,
                       const float* __restrict__ trans) {
    int b = blockIdx.x;
    float s = 0.0f;
    for (int t = threadIdx.x; t < Tq; t += blockDim.x) {
        if (x[b * Tq + t] > 0) {
            int cur = y0[b * Tq + t];
            int prev = (t == 0) ? 1 : y0[b * Tq + t - 1];
            s += g_y[((size_t)t * Bq + b) * NT + cur] + trans[cur * NT + prev];
        }
    }
    __shared__ float red[256];
    red[threadIdx.x] = s;
    __syncthreads();
    for (int k = 128; k > 0; k >>= 1) {
        if (threadIdx.x < k) red[threadIdx.x] += red[threadIdx.x + k];
        __syncthreads();
    }
    if (threadIdx.x == 0) g_gold[b] = red[0];
}

// ---------------- CRF forward ----------------
__global__ void k_crf(const int* __restrict__ x, const float* __restrict__ trans) {
    int b = blockIdx.x;
    int tag = threadIdx.x;
    __shared__ float st[NT * NT];
    __shared__ float ss[NT];
    for (int i = tag; i < NT * NT; i += 32) st[i] = trans[i];

    int len = 0;
    for (int t = tag; t < Tq; t += 32) len += (x[b * Tq + t] > 0) ? 1 : 0;
#pragma unroll
    for (int o = 16; o; o >>= 1) len += __shfl_xor_sync(0xffffffffu, len, o);

    float sc = (tag == 1) ? 0.0f : NEGV;
    ss[tag] = sc;
    __syncwarp();

    for (int t = 0; t < len; t++) {
        float emit = g_y[((size_t)t * Bq + b) * NT + tag];
        float mx = -3.4e38f;
#pragma unroll
        for (int p = 0; p < NT; p++) {
            float v = ss[p] + st[tag * NT + p];
            mx = fmaxf(mx, v);
        }
        float sum = 0.0f;
#pragma unroll
        for (int p = 0; p < NT; p++)
            sum += __expf(ss[p] + st[tag * NT + p] - mx);
        sc = emit + mx + __logf(sum);
        __syncwarp();
        ss[tag] = sc;
        __syncwarp();
    }

    float mx = sc;
#pragma unroll
    for (int o = 16; o; o >>= 1) mx = fmaxf(mx, __shfl_xor_sync(0xffffffffu, mx, o));
    float z;
    if (len < Tq) {
        z = mx + __logf(32.0f);
    } else {
        float sum = __expf(sc - mx);
#pragma unroll
        for (int o = 16; o; o >>= 1) sum += __shfl_xor_sync(0xffffffffu, sum, o);
        z = mx + __logf(sum);
    }
    if (tag == 0) g_Z[b] = z;
}

__global__ void k_final(float* __restrict__ out) {
    float s = 0.0f;
    for (int b = 0; b < Bq; b++) s += g_Z[b] - g_gold[b];
    out[0] = s / (float)Bq;
}

// ---------------- host launcher ----------------
extern "C" void kernel_launch(void* const* d_in, const int* in_sizes, int n_in,
                              void* d_out, int out_size) {
    (void)in_sizes; (void)n_in; (void)out_size;
    const int*   x     = (const int*)d_in[0];
    const int*   y0    = (const int*)d_in[1];
    const float* embw  = (const float*)d_in[2];
    const float* Wih0  = (const float*)d_in[3];
    const float* Whh0  = (const float*)d_in[4];
    const float* bih0  = (const float*)d_in[5];
    const float* bhh0  = (const float*)d_in[6];
    const float* Wih1  = (const float*)d_in[7];
    const float* Whh1  = (const float*)d_in[8];
    const float* bih1  = (const float*)d_in[9];
    const float* bhh1  = (const float*)d_in[10];
    const float* W_out = (const float*)d_in[11];
    const float* b_out = (const float*)d_in[12];
    const float* trans = (const float*)d_in[13];
    const float* h0    = (const float*)d_in[14];
    const float* c0    = (const float*)d_in[15];
    float* out = (float*)d_out;

    const int lstm_smem = (32000 + 4000 + 8 * SR_KS) * sizeof(float);  // ~163 KB
    cudaFuncSetAttribute(k_lstm, cudaFuncAttributeMaxDynamicSharedMemorySize, lstm_smem);

    k_embed<<<(Tq * Bq * Eq + 255) / 256, 256>>>(x, embw);

    {
        dim3 grid((G4 + 63) / 64, (Tq * Bq) / 64, 2);
        k_gemm<<<grid, 256>>>(0, Wih0, bih0, bhh0);
    }

    k_reset<<<1, 128>>>();
    k_lstm<<<NBLK, RTHR, lstm_smem>>>(0, Whh0, h0, c0, x);

    {
        dim3 grid((G4 + 63) / 64, (Tq * Bq) / 64, 2);
        k_gemm<<<grid, 256>>>(1, Wih1, bih1, bhh1);
    }

    k_reset<<<1, 128>>>();
    k_lstm<<<NBLK, RTHR, lstm_smem>>>(1, Whh1, h0, c0, x);

    k_outproj<<<(Tq * Bq) / 8, 256>>>(W_out, b_out);

    k_gold<<<Bq, 256>>>(x, y0, trans);
    k_crf<<<Bq, 32>>>(x, trans);
    k_final<<<1, 1>>>(out);
}